// round 3
// baseline (speedup 1.0000x reference)
#include <cuda_runtime.h>
#include <math.h>
#include <stdint.h>

#define SEQ   512
#define HID   512
#define IN0   1088
#define IN1   1024
#define GATES 2048
#define MLPH  100
#define PAIRD 2048
#define RCTAS 64   // CTAs per LSTM direction

// ---------------- device scratch (no allocations allowed) ----------------
__device__ float g_x0[SEQ * IN0];            // embeddings concat
__device__ float g_xw0[SEQ * GATES];         // xw fwd (current layer)
__device__ float g_xw1[SEQ * GATES];         // xw bwd (current layer)
__device__ float g_h0[SEQ * 2 * HID];        // layer0 output [t][fwd|bwd]
__device__ float g_h1[SEQ * 2 * HID];        // layer1 output
__device__ float g_sh[SEQ * MLPH];
__device__ float g_sm[SEQ * MLPH];
__device__ float g_scores[SEQ * SEQ];
__device__ unsigned g_cnt[2];                // per-direction barrier counters (zero-init)

// ---------------- helpers ----------------
__device__ __forceinline__ unsigned ld_acq(const unsigned* p) {
    unsigned v;
    asm volatile("ld.acquire.gpu.u32 %0, [%1];" : "=r"(v) : "l"(p) : "memory");
    return v;
}
__device__ __forceinline__ float sigmoidf_(float x) {
    return 1.0f / (1.0f + expf(-x));
}

// ---------------- embeddings ----------------
__global__ void embed_kernel(const int* __restrict__ wi, const int* __restrict__ pi,
                             const float* __restrict__ we, const float* __restrict__ pe) {
    int t = blockIdx.x;
    int w = wi[t], p = pi[t];
    const float* wr = we + (size_t)w * 1024;
    const float* pr = pe + (size_t)p * 64;
    float* out = g_x0 + (size_t)t * IN0;
    for (int i = threadIdx.x; i < 1024; i += blockDim.x) out[i] = wr[i];
    for (int i = threadIdx.x; i < 64; i += blockDim.x) out[1024 + i] = pr[i];
}

// ---------------- generic tiled GEMM: C[M,N] = A[M,K] * B[N,K]^T (+bias) ----------------
// BM=64, BN=64, BK=16, 256 threads, 4x4 register tile. K must be a multiple of 16.
__global__ void gemm_nt(const float* __restrict__ A, int lda,
                        const float* __restrict__ B, int ldb,
                        const float* __restrict__ bias,
                        float* __restrict__ C, int ldc,
                        int M, int N, int K) {
    __shared__ __align__(16) float As[16][68];
    __shared__ __align__(16) float Bs[16][68];
    int bm = blockIdx.y * 64, bn = blockIdx.x * 64;
    int tid = threadIdx.x;
    int tx = tid & 15, ty = tid >> 4;
    int lr = tid >> 2;          // 0..63: row within tile
    int lk = (tid & 3) * 4;     // k offset within 16

    float acc[4][4];
#pragma unroll
    for (int i = 0; i < 4; i++)
#pragma unroll
        for (int j = 0; j < 4; j++) acc[i][j] = 0.f;

    for (int k0 = 0; k0 < K; k0 += 16) {
        {
            int row = bm + lr;
            float4 v = make_float4(0.f, 0.f, 0.f, 0.f);
            if (row < M) v = *(const float4*)(A + (size_t)row * lda + k0 + lk);
            As[lk + 0][lr] = v.x; As[lk + 1][lr] = v.y; As[lk + 2][lr] = v.z; As[lk + 3][lr] = v.w;
            int rowb = bn + lr;
            float4 u = make_float4(0.f, 0.f, 0.f, 0.f);
            if (rowb < N) u = *(const float4*)(B + (size_t)rowb * ldb + k0 + lk);
            Bs[lk + 0][lr] = u.x; Bs[lk + 1][lr] = u.y; Bs[lk + 2][lr] = u.z; Bs[lk + 3][lr] = u.w;
        }
        __syncthreads();
#pragma unroll
        for (int k = 0; k < 16; k++) {
            float4 a4 = *(const float4*)&As[k][ty * 4];
            float4 b4 = *(const float4*)&Bs[k][tx * 4];
            float a[4] = {a4.x, a4.y, a4.z, a4.w};
            float b[4] = {b4.x, b4.y, b4.z, b4.w};
#pragma unroll
            for (int i = 0; i < 4; i++)
#pragma unroll
                for (int j = 0; j < 4; j++) acc[i][j] = fmaf(a[i], b[j], acc[i][j]);
        }
        __syncthreads();
    }
#pragma unroll
    for (int i = 0; i < 4; i++) {
        int r = bm + ty * 4 + i;
        if (r >= M) continue;
#pragma unroll
        for (int j = 0; j < 4; j++) {
            int c = bn + tx * 4 + j;
            if (c < N) C[(size_t)r * ldc + c] = acc[i][j] + (bias ? bias[c] : 0.f);
        }
    }
}

// ---------------- LSTM layer recurrence (both directions, persistent, grid barrier) ----------------
// grid = 128 CTAs (64 fwd, 64 bwd), 256 threads. Each CTA owns 8 h-indices (32 z rows).
// Dynamic smem: sW[32][513] + sh[512] + zp[256]
__global__ void lstm_layer(const float* __restrict__ whh_f, const float* __restrict__ whh_b,
                           const float* __restrict__ xw_f, const float* __restrict__ xw_b,
                           float* __restrict__ hout) {
    extern __shared__ float smem[];
    float* sW = smem;                  // 32 * 513
    float* sh = smem + 32 * 513;       // 512
    float* zp = sh + 512;              // 8 * 32

    int dir = blockIdx.x >> 6;
    int j = blockIdx.x & 63;
    int hbase = j * 8;
    const float* W = dir ? whh_b : whh_f;
    const float* xw = dir ? xw_b : xw_f;
    int tid = threadIdx.x;

    // load this CTA's 32 W_hh rows into smem (row rr = g*8+k -> global row g*512+hbase+k)
    {
        int rr = tid >> 3, part = tid & 7;
        int g = rr >> 3, k = rr & 7;
        const float* src = W + (size_t)(g * 512 + hbase + k) * 512 + part * 64;
        float* dst = sW + rr * 513 + part * 64;
#pragma unroll
        for (int i = 0; i < 64; i += 4) {
            float4 v = *(const float4*)(src + i);
            dst[i] = v.x; dst[i + 1] = v.y; dst[i + 2] = v.z; dst[i + 3] = v.w;
        }
    }

    float c_state = 0.f;           // owned by threads 0..7
    int row = tid & 31;            // z row within CTA
    int ck = tid >> 5;             // K chunk 0..7
    const int base = ck * 64;
    unsigned* cnt = &g_cnt[dir];

    for (int t = 0; t < 512; t++) {
        int pos = dir ? (511 - t) : t;

        // prefetch gate inputs (independent of h)
        float xg0 = 0.f, xg1 = 0.f, xg2 = 0.f, xg3 = 0.f;
        if (tid < 8) {
            const float* xr = xw + (size_t)pos * GATES + hbase + tid;
            xg0 = __ldg(xr);
            xg1 = __ldg(xr + 512);
            xg2 = __ldg(xr + 1024);
            xg3 = __ldg(xr + 1536);
        }

        // load h_prev into smem
        if (t == 0) {
            sh[tid] = 0.f; sh[tid + 256] = 0.f;
        } else {
            int ppos = dir ? (pos + 1) : (t - 1);
            const float* hp = hout + (size_t)ppos * 1024 + dir * 512;
            sh[tid] = __ldcg(hp + tid);
            sh[tid + 256] = __ldcg(hp + tid + 256);
        }
        __syncthreads();

        // matvec partial: row dot over chunk ck (64 elems), 4-way ILP
        {
            const float* wrow = sW + row * 513 + base;
            const float* hv = sh + base;
            float a0 = 0.f, a1 = 0.f, a2 = 0.f, a3 = 0.f;
#pragma unroll
            for (int i = 0; i < 64; i += 4) {
                a0 = fmaf(wrow[i + 0], hv[i + 0], a0);
                a1 = fmaf(wrow[i + 1], hv[i + 1], a1);
                a2 = fmaf(wrow[i + 2], hv[i + 2], a2);
                a3 = fmaf(wrow[i + 3], hv[i + 3], a3);
            }
            zp[ck * 32 + row] = (a0 + a1) + (a2 + a3);
        }
        __syncthreads();

        // gates & state update by threads 0..7 (thread k handles h index hbase+k)
        if (tid < 8) {
            float z[4] = {xg0, xg1, xg2, xg3};
#pragma unroll
            for (int g = 0; g < 4; g++) {
#pragma unroll
                for (int c = 0; c < 8; c++) z[g] += zp[c * 32 + g * 8 + tid];
            }
            float gi = sigmoidf_(z[0]);
            float gf = sigmoidf_(z[1]);
            float gg = tanhf(z[2]);
            float go = sigmoidf_(z[3]);
            c_state = gf * c_state + gi * gg;
            float h = go * tanhf(c_state);
            hout[(size_t)pos * 1024 + dir * 512 + hbase + tid] = h;
        }
        __syncthreads();

        // inter-CTA barrier (per direction), monotonic counter
        if (tid == 0) {
            __threadfence();
            atomicAdd(cnt, 1u);
            if (t < 511) {
                unsigned target = (unsigned)(t + 1) * RCTAS;
                while (ld_acq(cnt) < target) { }
            } else if (j == 0) {
                // exit protocol: wait for all arrivals, then reset for next launch/replay
                while (ld_acq(cnt) < 512u * RCTAS) { }
                atomicExch(cnt, 0u);
            }
        }
        __syncthreads();
    }
}

// ---------------- pairwise MLP edge scores ----------------
// scores[h][m] = sum_j tanh(sh[h][j] + sm[m][j] + b1[j]) * W2[j] + b2
__global__ void pair_score(const float* __restrict__ b1, const float* __restrict__ W2,
                           const float* __restrict__ b2) {
    __shared__ float Sh[32][101];
    __shared__ float Sm[32][101];
    __shared__ float sb1[MLPH], sw2[MLPH];
    int bh = blockIdx.y * 32, bm = blockIdx.x * 32;
    int tid = threadIdx.x;
    for (int i = tid; i < 32 * MLPH; i += 256) {
        int r = i / MLPH, c = i % MLPH;
        Sh[r][c] = g_sh[(size_t)(bh + r) * MLPH + c];
        Sm[r][c] = g_sm[(size_t)(bm + r) * MLPH + c];
    }
    if (tid < MLPH) { sb1[tid] = b1[tid]; sw2[tid] = W2[tid]; }
    __syncthreads();

    int tx = tid & 15, ty = tid >> 4;
    int h0 = ty * 2, m0 = tx * 2;
    float acc00 = 0.f, acc01 = 0.f, acc10 = 0.f, acc11 = 0.f;
    for (int jx = 0; jx < MLPH; jx++) {
        float w = sw2[jx], bb = sb1[jx];
        float a0 = Sh[h0][jx] + bb;
        float a1 = Sh[h0 + 1][jx] + bb;
        float c0 = Sm[m0][jx];
        float c1 = Sm[m0 + 1][jx];
        acc00 = fmaf(tanhf(a0 + c0), w, acc00);
        acc01 = fmaf(tanhf(a0 + c1), w, acc01);
        acc10 = fmaf(tanhf(a1 + c0), w, acc10);
        acc11 = fmaf(tanhf(a1 + c1), w, acc11);
    }
    float b2v = __ldg(b2);
    g_scores[(size_t)(bh + h0) * SEQ + bm + m0]         = acc00 + b2v;
    g_scores[(size_t)(bh + h0) * SEQ + bm + m0 + 1]     = acc01 + b2v;
    g_scores[(size_t)(bh + h0 + 1) * SEQ + bm + m0]     = acc10 + b2v;
    g_scores[(size_t)(bh + h0 + 1) * SEQ + bm + m0 + 1] = acc11 + b2v;
}

// ---------------- softmax over axis 0 (over h, per column m) ----------------
__global__ void softmax0(float* __restrict__ out) {
    int m = blockIdx.x;
    int tid = threadIdx.x;  // 128
    float v[4];
#pragma unroll
    for (int i = 0; i < 4; i++) v[i] = g_scores[(size_t)(tid + 128 * i) * SEQ + m];
    float mx = fmaxf(fmaxf(v[0], v[1]), fmaxf(v[2], v[3]));
    __shared__ float red[128];
    red[tid] = mx; __syncthreads();
    for (int o = 64; o > 0; o >>= 1) {
        if (tid < o) red[tid] = fmaxf(red[tid], red[tid + o]);
        __syncthreads();
    }
    mx = red[0]; __syncthreads();
    float e[4]; float ssum = 0.f;
#pragma unroll
    for (int i = 0; i < 4; i++) { e[i] = expf(v[i] - mx); ssum += e[i]; }
    red[tid] = ssum; __syncthreads();
    for (int o = 64; o > 0; o >>= 1) {
        if (tid < o) red[tid] += red[tid + o];
        __syncthreads();
    }
    float inv = 1.f / red[0];
#pragma unroll
    for (int i = 0; i < 4; i++) out[(size_t)(tid + 128 * i) * SEQ + m] = e[i] * inv;
}

// ---------------- launch ----------------
extern "C" void kernel_launch(void* const* d_in, const int* in_sizes, int n_in,
                              void* d_out, int out_size) {
    const int*   wi  = (const int*)d_in[0];
    const int*   pi  = (const int*)d_in[1];
    const float* we  = (const float*)d_in[2];
    const float* pe  = (const float*)d_in[3];
    const float* wih0f = (const float*)d_in[4];
    const float* whh0f = (const float*)d_in[5];
    const float* b0f   = (const float*)d_in[6];
    const float* wih0b = (const float*)d_in[7];
    const float* whh0b = (const float*)d_in[8];
    const float* b0b   = (const float*)d_in[9];
    const float* wih1f = (const float*)d_in[10];
    const float* whh1f = (const float*)d_in[11];
    const float* b1f   = (const float*)d_in[12];
    const float* wih1b = (const float*)d_in[13];
    const float* whh1b = (const float*)d_in[14];
    const float* b1b   = (const float*)d_in[15];
    const float* W1    = (const float*)d_in[16];
    const float* b1    = (const float*)d_in[17];
    const float* W2    = (const float*)d_in[18];
    const float* b2    = (const float*)d_in[19];
    float* out = (float*)d_out;

    // device-symbol addresses for the generic GEMM
    float *p_x0, *p_xw0, *p_xw1, *p_h0, *p_h1, *p_sh, *p_sm;
    cudaGetSymbolAddress((void**)&p_x0, g_x0);
    cudaGetSymbolAddress((void**)&p_xw0, g_xw0);
    cudaGetSymbolAddress((void**)&p_xw1, g_xw1);
    cudaGetSymbolAddress((void**)&p_h0, g_h0);
    cudaGetSymbolAddress((void**)&p_h1, g_h1);
    cudaGetSymbolAddress((void**)&p_sh, g_sh);
    cudaGetSymbolAddress((void**)&p_sm, g_sm);

    const int lstm_smem = (32 * 513 + 512 + 8 * 32) * (int)sizeof(float);
    cudaFuncSetAttribute(lstm_layer, cudaFuncAttributeMaxDynamicSharedMemorySize, lstm_smem);

    // 1. embeddings
    embed_kernel<<<SEQ, 256>>>(wi, pi, we, pe);

    // 2. layer0 input GEMMs: xw = x0 @ w_ih^T + b
    {
        dim3 grid(GATES / 64, SEQ / 64);
        gemm_nt<<<grid, 256>>>(p_x0, IN0, wih0f, IN0, b0f, p_xw0, GATES, SEQ, GATES, IN0);
        gemm_nt<<<grid, 256>>>(p_x0, IN0, wih0b, IN0, b0b, p_xw1, GATES, SEQ, GATES, IN0);
    }

    // 3. layer0 recurrence
    lstm_layer<<<2 * RCTAS, 256, lstm_smem>>>(whh0f, whh0b, p_xw0, p_xw1, p_h0);

    // 4. layer1 input GEMMs
    {
        dim3 grid(GATES / 64, SEQ / 64);
        gemm_nt<<<grid, 256>>>(p_h0, IN1, wih1f, IN1, b1f, p_xw0, GATES, SEQ, GATES, IN1);
        gemm_nt<<<grid, 256>>>(p_h0, IN1, wih1b, IN1, b1b, p_xw1, GATES, SEQ, GATES, IN1);
    }

    // 5. layer1 recurrence
    lstm_layer<<<2 * RCTAS, 256, lstm_smem>>>(whh1f, whh1b, p_xw0, p_xw1, p_h1);

    // 6. MLP projections: sh = h1 @ W1[:, :1024]^T, sm = h1 @ W1[:, 1024:]^T
    //    NOTE: W1 rows have stride PAIRD=2048 (W1 is [100, 2048]) — ldb must be 2048.
    {
        dim3 grid((MLPH + 63) / 64, SEQ / 64);
        gemm_nt<<<grid, 256>>>(p_h1, 2 * HID, W1, PAIRD, nullptr, p_sh, MLPH, SEQ, MLPH, 2 * HID);
        gemm_nt<<<grid, 256>>>(p_h1, 2 * HID, W1 + 1024, PAIRD, nullptr, p_sm, MLPH, SEQ, MLPH, 2 * HID);
    }

    // 7. pairwise scores
    {
        dim3 grid(SEQ / 32, SEQ / 32);
        pair_score<<<grid, 256>>>(b1, W2, b2);
    }

    // 8. softmax over heads (axis 0)
    softmax0<<<SEQ, 128>>>(out);
}